// round 15
// baseline (speedup 1.0000x reference)
#include <cuda_runtime.h>

// Fixed problem shapes.
#define Bdim    16
#define Cch     313
#define HW      16384
#define CHW     (Cch * HW)
#define NPIX    (Bdim * HW)          // 262144
#define Kk      5
#define THREADS 128
#define NITEMS  (NPIX / 4)           // 65536 float4 work items
#define NBLK    592                  // 148 SMs * 4 CTAs -> perfectly balanced
#define PF      8                    // prefetch ring depth

typedef unsigned long long ull;

// Scratch for deterministic single-launch reduction (no allocations allowed).
__device__ float        g_partials[NBLK];
__device__ unsigned int g_count;     // zero-init; last block re-arms it each launch

// ---------- packed f32x2 helpers (sm_103a native) ----------
__device__ __forceinline__ ull f2mul(ull a, ull b) {
    ull d; asm("mul.rn.f32x2 %0, %1, %2;" : "=l"(d) : "l"(a), "l"(b)); return d;
}
__device__ __forceinline__ ull f2add(ull a, ull b) {
    ull d; asm("add.rn.f32x2 %0, %1, %2;" : "=l"(d) : "l"(a), "l"(b)); return d;
}
__device__ __forceinline__ ull f2fma(ull a, ull b, ull c) {
    ull d; asm("fma.rn.f32x2 %0, %1, %2, %3;" : "=l"(d) : "l"(a), "l"(b), "l"(c)); return d;
}
__device__ __forceinline__ void upk(ull v, unsigned& lo, unsigned& hi) {
    asm("mov.b64 {%0, %1}, %2;" : "=r"(lo), "=r"(hi) : "l"(v));
}
__device__ __forceinline__ ull pk(unsigned lo, unsigned hi) {
    ull r; asm("mov.b64 %0, {%1, %2};" : "=l"(r) : "r"(lo), "r"(hi)); return r;
}
__device__ __forceinline__ ull rep(float x) {
    unsigned b = __float_as_uint(x); return ((ull)b << 32) | b;
}

// Branchless packed exp(x) = 2^(x*log2e) for two floats at once.
// Rounding via the 1.5*2^23 magic constant; exponent splice via integer add.
// Valid for |x| <~ 80 (here |x| <= ~7). Poly rel err ~2.4e-6.
__device__ __forceinline__ ull fast_exp2x(ull x) {
    const ull C_L2E  = rep(1.4426950408889634f);
    const ull C_MAG  = rep(12582912.0f);
    const ull C_NMAG = rep(-12582912.0f);
    const ull C_N1   = rep(-1.0f);
    ull t = f2mul(x, C_L2E);
    ull r = f2add(t, C_MAG);
    ull s = f2add(r, C_NMAG);
    ull f = f2fma(s, C_N1, t);          // f = t - round(t), in [-0.5, 0.5]
    ull p = rep(1.3333558146e-3f);
    p = f2fma(p, f, rep(9.6181291076e-3f));
    p = f2fma(p, f, rep(5.5504108664e-2f));
    p = f2fma(p, f, rep(2.4022650696e-1f));
    p = f2fma(p, f, rep(6.9314718056e-1f));
    p = f2fma(p, f, rep(1.0f));
    unsigned rlo, rhi, plo, phi;
    upk(r, rlo, rhi);
    upk(p, plo, phi);
    return pk(plo + (rlo << 23), phi + (rhi << 23));
}

__global__ __launch_bounds__(THREADS, 4)
void binned_color_loss_fused(const float* __restrict__ pred,
                             const int* __restrict__ binned,
                             const int* __restrict__ knn_idx,
                             const float* __restrict__ knn_w,
                             const float* __restrict__ weights,
                             float* __restrict__ out) {
    __shared__ int   s_idx[Cch * Kk];
    __shared__ float s_w[Cch * Kk];
    __shared__ float s_cw[Cch];       // per-bin outer weight
    __shared__ float s_ws[Cch];       // per-bin knn weight sum (~1.0)
    __shared__ float s_red[THREADS];
    __shared__ int   s_last;

    // ---- Stage tiny lookup tables into SMEM (clamp: trap -> wrong-answer) ----
    for (int i = threadIdx.x; i < Cch * Kk; i += THREADS) {
        int c = knn_idx[i];
        s_idx[i] = min(max(c, 0), Cch - 1);
        s_w[i]   = knn_w[i];
    }
    for (int i = threadIdx.x; i < Cch; i += THREADS) {
        s_cw[i] = weights[i];
        float ws = 0.f;
        #pragma unroll
        for (int k = 0; k < Kk; ++k) ws += knn_w[i * Kk + k];
        s_ws[i] = ws;
    }
    __syncthreads();

    // ---- Balanced contiguous work split: every SM owns ~443 items ----
    const int ibase = (int)(((long long)blockIdx.x * NITEMS) / NBLK);
    const int iend  = (int)(((long long)(blockIdx.x + 1) * NITEMS) / NBLK);
    const bool active = (ibase + threadIdx.x) < iend;    // 110-111 of 128 lanes
    const int item = min(ibase + threadIdx.x, NITEMS - 1);

    const int p   = item * 4;
    const int b   = p >> 14;            // / HW
    const int rem = p & (HW - 1);
    const float* base = pred + (size_t)b * CHW + rem;
    const ulonglong2* basev = reinterpret_cast<const ulonglong2*>(base);
    const size_t cstride = HW / 4;      // channel stride in 16B units

    // ---- Gather-first: dot_j = sum_k w_k * x_k does NOT need lse.
    //      Issue the 20 scattered loads up front; their latency hides
    //      behind the 50us streaming pass that follows. ----
    const int4 bv = *reinterpret_cast<const int4*>(binned + (size_t)b * HW + rem);
    int tt[4];
    tt[0] = min(max(bv.x, 0), Cch - 1);
    tt[1] = min(max(bv.y, 0), Cch - 1);
    tt[2] = min(max(bv.z, 0), Cch - 1);
    tt[3] = min(max(bv.w, 0), Cch - 1);
    float dot[4];
    #pragma unroll
    for (int j = 0; j < 4; ++j) {
        const int t = tt[j];
        float d = 0.f;
        #pragma unroll
        for (int k = 0; k < Kk; ++k) {
            const int c = s_idx[t * Kk + k];
            const float x = __ldg(base + (size_t)c * HW + j);
            d = fmaf(s_w[t * Kk + k], x, d);
        }
        dot[j] = d;
    }

    // ---- Streaming pass: sum(exp) over channels, 8-deep prefetch ring ----
    // (no max subtraction: |pred| <= ~7, sum <= 313*e^7 — fp32 safe)
    ull axy = 0ull, azw = 0ull;          // packed 0.0f accumulators
    ulonglong2 buf[PF];
    #pragma unroll
    for (int i = 0; i < PF; ++i) buf[i] = basev[(size_t)i * cstride];

    const int NBF = (Cch / PF) * PF;     // 312 channels in full blocks
    for (int cb = 0; cb < NBF; cb += PF) {
        #pragma unroll
        for (int i = 0; i < PF; ++i) {
            ulonglong2 v = buf[i];
            const int cn = cb + PF + i;
            if (cn < Cch) buf[i] = basev[(size_t)cn * cstride];
            axy = f2add(axy, fast_exp2x(v.x));
            azw = f2add(azw, fast_exp2x(v.y));
        }
    }
    #pragma unroll
    for (int i = 0; i < Cch - NBF; ++i) {  // tail channel 312, already in buf[0]
        axy = f2add(axy, fast_exp2x(buf[i].x));
        azw = f2add(azw, fast_exp2x(buf[i].y));
    }

    unsigned bx, by, bz, bw;
    upk(axy, bx, by);
    upk(azw, bz, bw);
    // sum_k w_k (x_k - lse) = dot - lse * sum(w)
    float partial =
          fmaf(-__logf(__uint_as_float(bx)), s_ws[tt[0]], dot[0]) * s_cw[tt[0]]
        + fmaf(-__logf(__uint_as_float(by)), s_ws[tt[1]], dot[1]) * s_cw[tt[1]]
        + fmaf(-__logf(__uint_as_float(bz)), s_ws[tt[2]], dot[2]) * s_cw[tt[2]]
        + fmaf(-__logf(__uint_as_float(bw)), s_ws[tt[3]], dot[3]) * s_cw[tt[3]];
    if (!active) partial = 0.f;

    // ---- Deterministic block reduction ----
    s_red[threadIdx.x] = partial;
    __syncthreads();
    #pragma unroll
    for (int off = THREADS / 2; off > 0; off >>= 1) {
        if (threadIdx.x < off) s_red[threadIdx.x] += s_red[threadIdx.x + off];
        __syncthreads();
    }

    // ---- Last-block finalize (deterministic: order fixed by index) ----
    if (threadIdx.x == 0) {
        g_partials[blockIdx.x] = s_red[0];
        __threadfence();
        unsigned t = atomicAdd(&g_count, 1u);
        s_last = (t == (unsigned)(gridDim.x - 1));
    }
    __syncthreads();
    if (s_last) {
        float v = 0.f;
        for (int i = threadIdx.x; i < NBLK; i += THREADS) v += g_partials[i];
        s_red[threadIdx.x] = v;
        __syncthreads();
        #pragma unroll
        for (int off = THREADS / 2; off > 0; off >>= 1) {
            if (threadIdx.x < off) s_red[threadIdx.x] += s_red[threadIdx.x + off];
            __syncthreads();
        }
        if (threadIdx.x == 0) {
            out[0] = -s_red[0] / (float)NPIX;
            g_count = 0;                 // re-arm for the next graph replay
        }
    }
}

extern "C" void kernel_launch(void* const* d_in, const int* in_sizes, int n_in,
                              void* d_out, int out_size) {
    (void)in_sizes; (void)n_in; (void)out_size;
    const float* pred    = (const float*)d_in[0];
    // d_in[1] = _color (unused by the reference computation)
    const int*   binned  = (const int*)d_in[2];
    const int*   knn_idx = (const int*)d_in[3];
    const float* knn_w   = (const float*)d_in[4];
    const float* weights = (const float*)d_in[5];
    float* out = (float*)d_out;

    binned_color_loss_fused<<<NBLK, THREADS>>>(pred, binned, knn_idx, knn_w, weights, out);
}

// round 16
// speedup vs baseline: 1.0268x; 1.0268x over previous
#include <cuda_runtime.h>

// Fixed problem shapes.
#define Bdim    16
#define Cch     313
#define HW      16384
#define CHW     (Cch * HW)
#define NPIX    (Bdim * HW)          // 262144
#define Kk      5
#define THREADS 128
#define NITEMS  (NPIX / 4)           // 65536 float4 work items
#define NBLK    592                  // 148 SMs * 4 CTAs -> perfectly balanced
#define PF      8                    // prefetch ring depth

typedef unsigned long long ull;

// Scratch for deterministic single-launch reduction (no allocations allowed).
__device__ float        g_partials[NBLK];
__device__ unsigned int g_count;     // zero-init; last block re-arms it each launch

// ---------- packed f32x2 helpers (sm_103a native) ----------
__device__ __forceinline__ ull f2mul(ull a, ull b) {
    ull d; asm("mul.rn.f32x2 %0, %1, %2;" : "=l"(d) : "l"(a), "l"(b)); return d;
}
__device__ __forceinline__ ull f2add(ull a, ull b) {
    ull d; asm("add.rn.f32x2 %0, %1, %2;" : "=l"(d) : "l"(a), "l"(b)); return d;
}
__device__ __forceinline__ ull f2fma(ull a, ull b, ull c) {
    ull d; asm("fma.rn.f32x2 %0, %1, %2, %3;" : "=l"(d) : "l"(a), "l"(b), "l"(c)); return d;
}
__device__ __forceinline__ void upk(ull v, unsigned& lo, unsigned& hi) {
    asm("mov.b64 {%0, %1}, %2;" : "=r"(lo), "=r"(hi) : "l"(v));
}
__device__ __forceinline__ ull pk(unsigned lo, unsigned hi) {
    ull r; asm("mov.b64 %0, {%1, %2};" : "=l"(r) : "r"(lo), "r"(hi)); return r;
}
__device__ __forceinline__ ull rep(float x) {
    unsigned b = __float_as_uint(x); return ((ull)b << 32) | b;
}

// Branchless packed exp(x) = 2^(x*log2e) for two floats at once.
// Rounding via the 1.5*2^23 magic constant; exponent splice via integer add.
// Valid for |x| <~ 80 (here |x| <= ~7). Poly rel err ~2.4e-6.
__device__ __forceinline__ ull fast_exp2x(ull x) {
    const ull C_L2E  = rep(1.4426950408889634f);
    const ull C_MAG  = rep(12582912.0f);
    const ull C_NMAG = rep(-12582912.0f);
    const ull C_N1   = rep(-1.0f);
    ull t = f2mul(x, C_L2E);
    ull r = f2add(t, C_MAG);
    ull s = f2add(r, C_NMAG);
    ull f = f2fma(s, C_N1, t);          // f = t - round(t), in [-0.5, 0.5]
    ull p = rep(1.3333558146e-3f);
    p = f2fma(p, f, rep(9.6181291076e-3f));
    p = f2fma(p, f, rep(5.5504108664e-2f));
    p = f2fma(p, f, rep(2.4022650696e-1f));
    p = f2fma(p, f, rep(6.9314718056e-1f));
    p = f2fma(p, f, rep(1.0f));
    unsigned rlo, rhi, plo, phi;
    upk(r, rlo, rhi);
    upk(p, plo, phi);
    return pk(plo + (rlo << 23), phi + (rhi << 23));
}

__global__ __launch_bounds__(THREADS, 4)
void binned_color_loss_fused(const float* __restrict__ pred,
                             const int* __restrict__ binned,
                             const int* __restrict__ knn_idx,
                             const float* __restrict__ knn_w,
                             const float* __restrict__ weights,
                             float* __restrict__ out) {
    __shared__ int   s_idx[Cch * Kk];
    __shared__ float s_w[Cch * Kk];
    __shared__ float s_cw[Cch];       // per-bin outer weight
    __shared__ float s_ws[Cch];       // per-bin knn weight sum (~1.0)
    __shared__ float s_red[THREADS];
    __shared__ int   s_last;

    // ---- Stage tiny lookup tables into SMEM (clamp: trap -> wrong-answer) ----
    for (int i = threadIdx.x; i < Cch * Kk; i += THREADS) {
        int c = knn_idx[i];
        s_idx[i] = min(max(c, 0), Cch - 1);
        s_w[i]   = knn_w[i];
    }
    for (int i = threadIdx.x; i < Cch; i += THREADS) {
        s_cw[i] = weights[i];
        float ws = 0.f;
        #pragma unroll
        for (int k = 0; k < Kk; ++k) ws += knn_w[i * Kk + k];
        s_ws[i] = ws;
    }
    __syncthreads();

    // ---- Balanced contiguous work split: every SM owns ~443 items ----
    const int ibase = (int)(((long long)blockIdx.x * NITEMS) / NBLK);
    const int iend  = (int)(((long long)(blockIdx.x + 1) * NITEMS) / NBLK);
    const bool active = (ibase + threadIdx.x) < iend;    // 110-111 of 128 lanes
    const int item = min(ibase + threadIdx.x, NITEMS - 1);

    const int p   = item * 4;
    const int b   = p >> 14;            // / HW
    const int rem = p & (HW - 1);
    const float* base = pred + (size_t)b * CHW + rem;
    const ulonglong2* basev = reinterpret_cast<const ulonglong2*>(base);
    const size_t cstride = HW / 4;      // channel stride in 16B units

    // ---- Gather-first: dot_j = sum_k w_k * x_k does NOT need lse.
    //      Issue the 20 scattered loads up front; their latency hides
    //      behind the 50us streaming pass that follows. ----
    const int4 bv = *reinterpret_cast<const int4*>(binned + (size_t)b * HW + rem);
    int tt[4];
    tt[0] = min(max(bv.x, 0), Cch - 1);
    tt[1] = min(max(bv.y, 0), Cch - 1);
    tt[2] = min(max(bv.z, 0), Cch - 1);
    tt[3] = min(max(bv.w, 0), Cch - 1);
    float dot[4];
    #pragma unroll
    for (int j = 0; j < 4; ++j) {
        const int t = tt[j];
        float d = 0.f;
        #pragma unroll
        for (int k = 0; k < Kk; ++k) {
            const int c = s_idx[t * Kk + k];
            const float x = __ldg(base + (size_t)c * HW + j);
            d = fmaf(s_w[t * Kk + k], x, d);
        }
        dot[j] = d;
    }

    // ---- Streaming pass: sum(exp) over channels, 8-deep prefetch ring ----
    // (no max subtraction: |pred| <= ~7, sum <= 313*e^7 — fp32 safe)
    ull axy = 0ull, azw = 0ull;          // packed 0.0f accumulators
    ulonglong2 buf[PF];
    #pragma unroll
    for (int i = 0; i < PF; ++i) buf[i] = basev[(size_t)i * cstride];

    const int NBF = (Cch / PF) * PF;     // 312 channels in full blocks
    for (int cb = 0; cb < NBF; cb += PF) {
        #pragma unroll
        for (int i = 0; i < PF; ++i) {
            ulonglong2 v = buf[i];
            const int cn = cb + PF + i;
            if (cn < Cch) buf[i] = basev[(size_t)cn * cstride];
            axy = f2add(axy, fast_exp2x(v.x));
            azw = f2add(azw, fast_exp2x(v.y));
        }
    }
    #pragma unroll
    for (int i = 0; i < Cch - NBF; ++i) {  // tail channel 312, already in buf[0]
        axy = f2add(axy, fast_exp2x(buf[i].x));
        azw = f2add(azw, fast_exp2x(buf[i].y));
    }

    unsigned bx, by, bz, bw;
    upk(axy, bx, by);
    upk(azw, bz, bw);
    // sum_k w_k (x_k - lse) = dot - lse * sum(w)
    float partial =
          fmaf(-__logf(__uint_as_float(bx)), s_ws[tt[0]], dot[0]) * s_cw[tt[0]]
        + fmaf(-__logf(__uint_as_float(by)), s_ws[tt[1]], dot[1]) * s_cw[tt[1]]
        + fmaf(-__logf(__uint_as_float(bz)), s_ws[tt[2]], dot[2]) * s_cw[tt[2]]
        + fmaf(-__logf(__uint_as_float(bw)), s_ws[tt[3]], dot[3]) * s_cw[tt[3]];
    if (!active) partial = 0.f;

    // ---- Deterministic block reduction ----
    s_red[threadIdx.x] = partial;
    __syncthreads();
    #pragma unroll
    for (int off = THREADS / 2; off > 0; off >>= 1) {
        if (threadIdx.x < off) s_red[threadIdx.x] += s_red[threadIdx.x + off];
        __syncthreads();
    }

    // ---- Last-block finalize (deterministic: order fixed by index) ----
    if (threadIdx.x == 0) {
        g_partials[blockIdx.x] = s_red[0];
        __threadfence();
        unsigned t = atomicAdd(&g_count, 1u);
        s_last = (t == (unsigned)(gridDim.x - 1));
    }
    __syncthreads();
    if (s_last) {
        float v = 0.f;
        for (int i = threadIdx.x; i < NBLK; i += THREADS) v += g_partials[i];
        s_red[threadIdx.x] = v;
        __syncthreads();
        #pragma unroll
        for (int off = THREADS / 2; off > 0; off >>= 1) {
            if (threadIdx.x < off) s_red[threadIdx.x] += s_red[threadIdx.x + off];
            __syncthreads();
        }
        if (threadIdx.x == 0) {
            out[0] = -s_red[0] / (float)NPIX;
            g_count = 0;                 // re-arm for the next graph replay
        }
    }
}

extern "C" void kernel_launch(void* const* d_in, const int* in_sizes, int n_in,
                              void* d_out, int out_size) {
    (void)in_sizes; (void)n_in; (void)out_size;
    const float* pred    = (const float*)d_in[0];
    // d_in[1] = _color (unused by the reference computation)
    const int*   binned  = (const int*)d_in[2];
    const int*   knn_idx = (const int*)d_in[3];
    const float* knn_w   = (const float*)d_in[4];
    const float* weights = (const float*)d_in[5];
    float* out = (float*)d_out;

    binned_color_loss_fused<<<NBLK, THREADS>>>(pred, binned, knn_idx, knn_w, weights, out);
}

// round 17
// speedup vs baseline: 1.0347x; 1.0076x over previous
#include <cuda_runtime.h>

// Fixed problem shapes.
#define Bdim    16
#define Cch     313
#define HW      16384
#define CHW     (Cch * HW)
#define NPIX    (Bdim * HW)          // 262144
#define Kk      5
#define THREADS 128
#define NITEMS  (NPIX / 4)           // 65536 float4 work items
#define NBLK    592                  // 148 SMs * 4 CTAs -> perfectly balanced
#define PF      8                    // prefetch ring depth
#define NENT    (4 * Kk)             // 20 gather entries per thread
#define ESTRIDE 21                   // +1 sentinel slot; odd stride -> 2-way LDS conflicts only

typedef unsigned long long ull;

// Scratch for deterministic single-launch reduction (no allocations allowed).
__device__ float        g_partials[NBLK];
__device__ unsigned int g_count;     // zero-init; last block re-arms it each launch

// ---------- packed f32x2 helpers (sm_103a native) ----------
__device__ __forceinline__ ull f2mul(ull a, ull b) {
    ull d; asm("mul.rn.f32x2 %0, %1, %2;" : "=l"(d) : "l"(a), "l"(b)); return d;
}
__device__ __forceinline__ ull f2add(ull a, ull b) {
    ull d; asm("add.rn.f32x2 %0, %1, %2;" : "=l"(d) : "l"(a), "l"(b)); return d;
}
__device__ __forceinline__ ull f2fma(ull a, ull b, ull c) {
    ull d; asm("fma.rn.f32x2 %0, %1, %2, %3;" : "=l"(d) : "l"(a), "l"(b), "l"(c)); return d;
}
__device__ __forceinline__ void upk(ull v, unsigned& lo, unsigned& hi) {
    asm("mov.b64 {%0, %1}, %2;" : "=r"(lo), "=r"(hi) : "l"(v));
}
__device__ __forceinline__ ull pk(unsigned lo, unsigned hi) {
    ull r; asm("mov.b64 %0, {%1, %2};" : "=l"(r) : "r"(lo), "r"(hi)); return r;
}
__device__ __forceinline__ ull rep(float x) {
    unsigned b = __float_as_uint(x); return ((ull)b << 32) | b;
}

// Branchless packed exp(x) = 2^(x*log2e) for two floats at once.
// Rounding via the 1.5*2^23 magic constant; exponent splice via integer add.
// Valid for |x| <~ 80 (here |x| <= ~7). Poly rel err ~2.4e-6.
__device__ __forceinline__ ull fast_exp2x(ull x) {
    const ull C_L2E  = rep(1.4426950408889634f);
    const ull C_MAG  = rep(12582912.0f);
    const ull C_NMAG = rep(-12582912.0f);
    const ull C_N1   = rep(-1.0f);
    ull t = f2mul(x, C_L2E);
    ull r = f2add(t, C_MAG);
    ull s = f2add(r, C_NMAG);
    ull f = f2fma(s, C_N1, t);          // f = t - round(t), in [-0.5, 0.5]
    ull p = rep(1.3333558146e-3f);
    p = f2fma(p, f, rep(9.6181291076e-3f));
    p = f2fma(p, f, rep(5.5504108664e-2f));
    p = f2fma(p, f, rep(2.4022650696e-1f));
    p = f2fma(p, f, rep(6.9314718056e-1f));
    p = f2fma(p, f, rep(1.0f));
    unsigned rlo, rhi, plo, phi;
    upk(r, rlo, rhi);
    upk(p, plo, phi);
    return pk(plo + (rlo << 23), phi + (rhi << 23));
}

// Consume all gather entries with channel < climit. Their stream lines are
// L1/L2-resident (this thread loaded them within the last 1-2 PF blocks),
// so these LDGs generate no DRAM traffic.
#define DRAIN(climit)                                                        \
    {                                                                        \
        const unsigned _lim = ((unsigned)(climit)) << 2;                     \
        while ((unsigned)(ecur >> 32) < _lim) {                              \
            const unsigned _key = (unsigned)(ecur >> 32);                    \
            const float _coef = __uint_as_float((unsigned)ecur);             \
            gdot = fmaf(_coef,                                               \
                        __ldg(base + (size_t)(_key >> 2) * HW + (_key & 3)), \
                        gdot);                                               \
            ecur = ent[++ep];                                                \
        }                                                                    \
    }

__global__ __launch_bounds__(THREADS, 4)
void binned_color_loss_fused(const float* __restrict__ pred,
                             const int* __restrict__ binned,
                             const int* __restrict__ knn_idx,
                             const float* __restrict__ knn_w,
                             const float* __restrict__ weights,
                             float* __restrict__ out) {
    __shared__ ull   s_ent[THREADS * ESTRIDE];   // per-thread sorted gather lists
    __shared__ float s_cw[Cch];                  // per-bin outer weight
    __shared__ float s_ws[Cch];                  // per-bin knn weight sum
    __shared__ float s_red[THREADS];
    __shared__ int   s_last;

    // ---- Stage the tiny per-bin scalars ----
    for (int i = threadIdx.x; i < Cch; i += THREADS) {
        s_cw[i] = weights[i];
        float ws = 0.f;
        #pragma unroll
        for (int k = 0; k < Kk; ++k) ws += knn_w[i * Kk + k];
        s_ws[i] = ws;
    }

    // ---- Balanced contiguous work split: every SM owns ~443 items ----
    const int ibase = (int)(((long long)blockIdx.x * NITEMS) / NBLK);
    const int iend  = (int)(((long long)(blockIdx.x + 1) * NITEMS) / NBLK);
    const bool active = (ibase + threadIdx.x) < iend;    // 110-111 of 128 lanes
    const int item = min(ibase + threadIdx.x, NITEMS - 1);

    const int p   = item * 4;
    const int b   = p >> 14;            // / HW
    const int rem = p & (HW - 1);
    const float* base = pred + (size_t)b * CHW + rem;
    const ulonglong2* basev = reinterpret_cast<const ulonglong2*>(base);
    const size_t cstride = HW / 4;      // channel stride in 16B units

    // ---- Build this thread's 20 gather entries, sorted by channel ----
    // entry = (channel<<2 | pixel_j) in hi32, coeff = knn_w * bin_weight in lo32
    const int4 bv = *reinterpret_cast<const int4*>(binned + (size_t)b * HW + rem);
    int tt[4];
    tt[0] = min(max(bv.x, 0), Cch - 1);
    tt[1] = min(max(bv.y, 0), Cch - 1);
    tt[2] = min(max(bv.z, 0), Cch - 1);
    tt[3] = min(max(bv.w, 0), Cch - 1);

    ull* ent = &s_ent[threadIdx.x * ESTRIDE];
    #pragma unroll
    for (int j = 0; j < 4; ++j) {
        const int t = tt[j];
        const float cw = __ldg(weights + t);
        #pragma unroll
        for (int k = 0; k < Kk; ++k) {
            int c = __ldg(knn_idx + t * Kk + k);
            c = min(max(c, 0), Cch - 1);
            const float coeff = __ldg(knn_w + t * Kk + k) * cw;
            const unsigned key = ((unsigned)c << 2) | (unsigned)j;
            ent[j * Kk + k] = ((ull)key << 32) | (ull)__float_as_uint(coeff);
        }
    }
    ent[NENT] = 0xFFFFFFFF00000000ull;              // sentinel: key=huge, coeff=0
    // one-time insertion sort (amortized over the 313-channel stream)
    for (int i = 1; i < NENT; ++i) {
        ull v = ent[i];
        int q = i - 1;
        while (q >= 0 && ent[q] > v) { ent[q + 1] = ent[q]; --q; }
        ent[q + 1] = v;
    }
    int ep = 0;
    ull ecur = ent[0];
    float gdot = 0.f;
    __syncthreads();

    // ---- Streaming pass: sum(exp) + post-block entry drains ----
    // (no max subtraction: |pred| <= ~7, sum <= 313*e^7 — fp32 safe)
    ull axy = 0ull, azw = 0ull;          // packed 0.0f accumulators
    ulonglong2 buf[PF];
    #pragma unroll
    for (int i = 0; i < PF; ++i) buf[i] = basev[(size_t)i * cstride];

    const int NBF = (Cch / PF) * PF;     // 312 channels in full blocks
    for (int cb = 0; cb < NBF; cb += PF) {
        #pragma unroll
        for (int i = 0; i < PF; ++i) {
            ulonglong2 v = buf[i];
            const int cn = cb + PF + i;
            if (cn < Cch) buf[i] = basev[(size_t)cn * cstride];
            axy = f2add(axy, fast_exp2x(v.x));
            azw = f2add(azw, fast_exp2x(v.y));
        }
        DRAIN(cb + PF)                   // channels [0, cb+PF) are L1/L2-hot
    }
    #pragma unroll
    for (int i = 0; i < Cch - NBF; ++i) {  // tail channel 312, already in buf[0]
        axy = f2add(axy, fast_exp2x(buf[i].x));
        azw = f2add(azw, fast_exp2x(buf[i].y));
    }
    DRAIN(Cch)                            // final drain (sentinel stops the loop)

    unsigned bx, by, bz, bw;
    upk(axy, bx, by);
    upk(azw, bz, bw);
    // sum_k w_k (x_k - lse) summed over pixels = gdot - sum_j lse_j * ws_j * cw_j
    float partial = gdot
        - __logf(__uint_as_float(bx)) * s_ws[tt[0]] * s_cw[tt[0]]
        - __logf(__uint_as_float(by)) * s_ws[tt[1]] * s_cw[tt[1]]
        - __logf(__uint_as_float(bz)) * s_ws[tt[2]] * s_cw[tt[2]]
        - __logf(__uint_as_float(bw)) * s_ws[tt[3]] * s_cw[tt[3]];
    if (!active) partial = 0.f;

    // ---- Deterministic block reduction ----
    s_red[threadIdx.x] = partial;
    __syncthreads();
    #pragma unroll
    for (int off = THREADS / 2; off > 0; off >>= 1) {
        if (threadIdx.x < off) s_red[threadIdx.x] += s_red[threadIdx.x + off];
        __syncthreads();
    }

    // ---- Last-block finalize (deterministic: order fixed by index) ----
    if (threadIdx.x == 0) {
        g_partials[blockIdx.x] = s_red[0];
        __threadfence();
        unsigned t = atomicAdd(&g_count, 1u);
        s_last = (t == (unsigned)(gridDim.x - 1));
    }
    __syncthreads();
    if (s_last) {
        float v = 0.f;
        for (int i = threadIdx.x; i < NBLK; i += THREADS) v += g_partials[i];
        s_red[threadIdx.x] = v;
        __syncthreads();
        #pragma unroll
        for (int off = THREADS / 2; off > 0; off >>= 1) {
            if (threadIdx.x < off) s_red[threadIdx.x] += s_red[threadIdx.x + off];
            __syncthreads();
        }
        if (threadIdx.x == 0) {
            out[0] = -s_red[0] / (float)NPIX;
            g_count = 0;                 // re-arm for the next graph replay
        }
    }
}

extern "C" void kernel_launch(void* const* d_in, const int* in_sizes, int n_in,
                              void* d_out, int out_size) {
    (void)in_sizes; (void)n_in; (void)out_size;
    const float* pred    = (const float*)d_in[0];
    // d_in[1] = _color (unused by the reference computation)
    const int*   binned  = (const int*)d_in[2];
    const int*   knn_idx = (const int*)d_in[3];
    const float* knn_w   = (const float*)d_in[4];
    const float* weights = (const float*)d_in[5];
    float* out = (float*)d_out;

    binned_color_loss_fused<<<NBLK, THREADS>>>(pred, binned, knn_idx, knn_w, weights, out);
}